// round 16
// baseline (speedup 1.0000x reference)
#include <cuda_runtime.h>
#include <cuda_fp16.h>
#include <math.h>

// Problem constants
#define BQ      1024
#define DDIM    128
#define NKEYS   200000
#define HFDIM   168
#define TOPK    16
#define MTOP    48
#define CHUNK   2048
#define NCHUNKS 98           // 97*2048 + 1344; every 64-key tile full
#define QTILES  8
#define NPAIRS  (QTILES*NCHUNKS)   // 784
#define FTHR    128
#define GRID_F  444          // 3 blocks/SM persistent

// -------- filter kernel SMEM layout (bytes) --------
// [Ks fp16 2x64x136 (34816, unioned with Qs 128x136) | SimU u32 128x37 | work]
#define KBUF_B    17408
#define OFF_SIM   34816
#define OFF_WORK  53760
#define SMEM_SZ   53776

// -------- scratch --------
__device__ float g_qn[BQ * DDIM];
__device__ __half g_qh[BQ * DDIM];
__device__ __half g_khd[(size_t)NKEYS * DDIM];
__device__ float g_scale[NKEYS];
__device__ unsigned long long g_cand[(size_t)BQ * NCHUNKS * TOPK];
__device__ int g_ts64;
__device__ unsigned int g_work;

// -------- helpers --------
__device__ __forceinline__ unsigned int fkey(float f) {
    unsigned int u = __float_as_uint(f);
    return (u & 0x80000000u) ? ~u : (u | 0x80000000u);
}
__device__ __forceinline__ float funkey(unsigned int u) {
    return (u & 0x80000000u) ? __uint_as_float(u ^ 0x80000000u)
                             : __uint_as_float(~u);
}
__device__ __forceinline__ unsigned int fkey16(unsigned int h) {
    return (h & 0x8000u) ? (h ^ 0xFFFFu) : (h | 0x8000u);
}
__device__ __forceinline__ unsigned int unfkey16(unsigned int k16) {
    return (k16 & 0x8000u) ? (k16 ^ 0x8000u) : (k16 ^ 0xFFFFu);
}
__device__ __forceinline__ unsigned int su32(const void* p) {
    unsigned int r;
    asm("{.reg .u64 t; cvta.to.shared.u64 t, %1; cvt.u32.u64 %0, t;}"
        : "=r"(r) : "l"(p));
    return r;
}
__device__ __forceinline__ void cp16(unsigned int dst, const void* src) {
    asm volatile("cp.async.cg.shared.global [%0], [%1], 16;"
                 :: "r"(dst), "l"(src));
}
#define CP_COMMIT() asm volatile("cp.async.commit_group;")
#define CP_WAIT0()  asm volatile("cp.async.wait_group 0;" ::: "memory")

#define LDSM_X4(f, ad) \
    asm volatile("ldmatrix.sync.aligned.m8n8.x4.shared.b16 {%0,%1,%2,%3}, [%4];" \
        : "=r"((f)[0]), "=r"((f)[1]), "=r"((f)[2]), "=r"((f)[3]) : "r"(ad))
#define MMA_F16(c0, c1, a, b0, b1) \
    asm volatile("mma.sync.aligned.m16n8k16.row.col.f16.f16.f16.f16 " \
        "{%0,%1}, {%2,%3,%4,%5}, {%6,%7}, {%0,%1};" \
        : "+r"(c0), "+r"(c1) \
        : "r"((a)[0]), "r"((a)[1]), "r"((a)[2]), "r"((a)[3]), "r"(b0), "r"(b1))

// -------- kernel 0: detect ts dtype + reset work counter --------
__global__ void k_detect(const unsigned int* tsw) {
    if (threadIdx.x == 0) {
        int all0 = 1;
        for (int i = 0; i < 64; i++)
            if (tsw[2 * i + 1] != 0u) { all0 = 0; break; }
        g_ts64 = all0;
        g_work = 0u;
    }
}

// -------- kernel 1: normalize queries (fp32 + fp16) --------
__global__ void k_normq(const float* __restrict__ query) {
    int b = blockIdx.x;
    int d = threadIdx.x;
    float v = query[b * DDIM + d];
    float s = v * v;
    #pragma unroll
    for (int o = 16; o; o >>= 1) s += __shfl_xor_sync(0xffffffffu, s, o);
    __shared__ float ws[4];
    if ((d & 31) == 0) ws[d >> 5] = s;
    __syncthreads();
    float tot = ws[0] + ws[1] + ws[2] + ws[3];
    float n = fmaxf(sqrtf(tot), 1e-12f);
    float q = v / n;
    g_qn[b * DDIM + d] = q;
    g_qh[b * DDIM + d] = __float2half_rn(q);
}

// -------- kernel 2: per-key scale + fp16 decayed keys --------
__global__ void k_scale(const float* __restrict__ keys, const void* ts,
                        const int* gsp, int has_gs) {
    int gw = (blockIdx.x * blockDim.x + threadIdx.x) >> 5;
    int lane = threadIdx.x & 31;
    if (gw >= NKEYS) return;
    float4 a = ((const float4*)(keys + (size_t)gw * DDIM))[lane];
    float s = a.x * a.x + a.y * a.y + a.z * a.z + a.w * a.w;
    #pragma unroll
    for (int o = 16; o; o >>= 1) s += __shfl_xor_sync(0xffffffffu, s, o);
    float sc;
    if (lane == 0) {
        long long t = g_ts64 ? ((const long long*)ts)[gw]
                             : (long long)((const int*)ts)[gw];
        int gs = has_gs ? gsp[0] : 1000;
        float age = (float)(gs - (int)t);
        float dec = powf(0.995f, age);
        float nr = fmaxf(sqrtf(s), 1e-12f);
        sc = dec / nr;
        g_scale[gw] = sc;
    }
    sc = __shfl_sync(0xffffffffu, sc, 0);
    __half2 p0 = __floats2half2_rn(a.x * sc, a.y * sc);
    __half2 p1 = __floats2half2_rn(a.z * sc, a.w * sc);
    uint2 pk = make_uint2(*(unsigned int*)&p0, *(unsigned int*)&p1);
    *(uint2*)&g_khd[(size_t)gw * DDIM + lane * 4] = pk;
}

// -------- kernel 3: fp16 MMA filter, register top-16 + h2 prescreen ----
__global__ void __launch_bounds__(FTHR, 3)
k_filter() {
    extern __shared__ __align__(16) unsigned char sm[];
    __half* Ks  = (__half*)sm;                     // [2][64][136]
    __half* Qs  = (__half*)sm;                     // [128][136] (prologue union)
    unsigned int* SimU = (unsigned int*)(sm + OFF_SIM);  // [128][37]
    unsigned int* swork = (unsigned int*)(sm + OFF_WORK);

    unsigned int ks_base = su32(Ks);
    int tid  = threadIdx.x;
    int warp = tid >> 5;
    int lane = tid & 31;
    int q0 = warp * 32;
    int qr = lane >> 2;
    int qc = lane & 3;

    for (;;) {
        __syncthreads();
        if (tid == 0) *swork = atomicAdd(&g_work, 1u);
        __syncthreads();
        unsigned int p = *swork;
        if (p >= NPAIRS) break;
        int chunk = p >> 3;
        int qtile = p & 7;
        int qbase = qtile * 128;
        int c0 = chunk * CHUNK;
        int ntiles = (chunk == NCHUNKS - 1) ? 21 : 32;

        // register top-16 list (packed: fkey16(val)<<16 | (2047-localidx))
        unsigned int lst[TOPK];
        #pragma unroll
        for (int j = 0; j < TOPK; j++) lst[j] = 0u;

        // prologue: stage Q [128][128] fp16 through the K double-buffer region
        for (int i = tid; i < 128 * 16; i += FTHR) {
            int row = i >> 4, c = i & 15;
            *(uint4*)(Qs + row * 136 + c * 8) =
                *(const uint4*)(g_qh + (qbase + row) * DDIM + c * 8);
        }
        __syncthreads();
        unsigned int afr[16][4];
        #pragma unroll
        for (int s8 = 0; s8 < 8; s8++) {
            #pragma unroll
            for (int mi = 0; mi < 2; mi++) {
                int row = q0 + mi * 16 + (lane & 15);
                int col = s8 * 16 + ((lane >> 4) << 3);
                LDSM_X4(afr[mi * 8 + s8], su32(Qs + row * 136 + col));
            }
        }
        __syncthreads();   // A frags read before K tile 0 overwrites

        // issue K tile 0 into buffer 0
        #pragma unroll
        for (int it = 0; it < 8; it++) {
            int i = tid + it * FTHR;
            int row = i >> 4, c = i & 15;
            cp16(ks_base + row * 272 + c * 16,
                 g_khd + (size_t)(c0 + row) * DDIM + c * 8);
        }
        CP_COMMIT();

        for (int t = 0; t < ntiles; t++) {
            unsigned int kb = ks_base + (t & 1) * KBUF_B;
            CP_WAIT0();
            __syncthreads();   // tile t ready; all warps done with tile t-1

            if (t + 1 < ntiles) {
                int n1 = c0 + (t + 1) * 64;
                unsigned int ob = ks_base + ((t + 1) & 1) * KBUF_B;
                #pragma unroll
                for (int it = 0; it < 8; it++) {
                    int i = tid + it * FTHR;
                    int row = i >> 4, c = i & 15;
                    cp16(ob + row * 272 + c * 16,
                         g_khd + (size_t)(n1 + row) * DDIM + c * 8);
                }
            }
            CP_COMMIT();

            // fp16-acc MMA over 8 k-steps
            unsigned int acc[2][8][2];
            #pragma unroll
            for (int mi = 0; mi < 2; mi++)
                #pragma unroll
                for (int nt = 0; nt < 8; nt++) {
                    acc[mi][nt][0] = 0u;
                    acc[mi][nt][1] = 0u;
                }
            #pragma unroll
            for (int s8 = 0; s8 < 8; s8++) {
                unsigned int bb[4][4];
                int prow = (lane & 7) + ((lane >> 4) << 3);
                int pcol = s8 * 16 + (((lane >> 3) & 1) << 3);
                #pragma unroll
                for (int g = 0; g < 4; g++)
                    LDSM_X4(bb[g], kb + (g * 16 + prow) * 272 + pcol * 2);
                #pragma unroll
                for (int mi = 0; mi < 2; mi++) {
                    const unsigned int* a = afr[mi * 8 + s8];
                    #pragma unroll
                    for (int nt = 0; nt < 8; nt++) {
                        unsigned int b0 = bb[nt >> 1][(nt & 1) * 2];
                        unsigned int b1 = bb[nt >> 1][(nt & 1) * 2 + 1];
                        MMA_F16(acc[mi][nt][0], acc[mi][nt][1], a, b0, b1);
                    }
                }
            }

            // register rowmax per covered row (mx[mi*2+e] covers row qr+e*8+mi*16)
            float mx[4];
            #pragma unroll
            for (int mi = 0; mi < 2; mi++) {
                #pragma unroll
                for (int e = 0; e < 2; e++) {
                    __half2 m = *(__half2*)&acc[mi][0][e];
                    #pragma unroll
                    for (int nt = 1; nt < 8; nt++)
                        m = __hmax2(m, *(__half2*)&acc[mi][nt][e]);
                    float mv = fmaxf(__low2float(m), __high2float(m));
                    mv = fmaxf(mv, __shfl_xor_sync(0xffffffffu, mv, 1));
                    mv = fmaxf(mv, __shfl_xor_sync(0xffffffffu, mv, 2));
                    mx[mi * 2 + e] = mv;
                }
            }
            // route rowmax to owner lane (lane L owns row q0+L)
            int srcl = (lane & 7) * 4;
            float m0 = __shfl_sync(0xffffffffu, mx[0], srcl);
            float m1 = __shfl_sync(0xffffffffu, mx[1], srcl);
            float m2 = __shfl_sync(0xffffffffu, mx[2], srcl);
            float m3 = __shfl_sync(0xffffffffu, mx[3], srcl);
            int ksel = ((lane >> 4) << 1) | ((lane >> 3) & 1);
            float mymax = (ksel == 0) ? m0 : (ksel == 1) ? m1
                        : (ksel == 2) ? m2 : m3;
            unsigned int rowpk =
                (fkey16((unsigned int)__half_as_ushort(__float2half_rn(mymax)))
                 << 16) | 0x7FFu;
            unsigned int myflag = (rowpk > lst[TOPK - 1]) ? 1u : 0u;
            unsigned int flags = __ballot_sync(0xffffffffu, myflag);

            if (flags) {
                // predicated stores of flagged rows (u32 cols nt*4+qc)
                #pragma unroll
                for (int mi = 0; mi < 2; mi++)
                    #pragma unroll
                    for (int e = 0; e < 2; e++) {
                        int rr = qr + e * 8 + mi * 16;
                        if ((flags >> rr) & 1u) {
                            unsigned int* dst = SimU + (q0 + rr) * 37 + qc;
                            #pragma unroll
                            for (int nt = 0; nt < 8; nt++)
                                dst[nt * 4] = acc[mi][nt][e];
                        }
                    }
                __syncwarp();
                if (myflag) {
                    const unsigned int* rowu = SimU + (q0 + lane) * 37;
                    int tb = t * 64;
                    // threshold as half2 (tail value; >= keeps idx-tie candidates)
                    unsigned int tk = lst[TOPK - 1] >> 16;
                    unsigned int th = tk ? unfkey16(tk) : 0xFC00u;  // -inf if empty
                    __half2 thr2 = __half2half2(__ushort_as_half((unsigned short)th));
                    for (int j2 = 0; j2 < 32; j2++) {
                        unsigned int u = rowu[j2];
                        unsigned int msk = __hge2_mask(*(__half2*)&u, thr2);
                        if (!msk) continue;
                        int kcol = ((j2 >> 2) << 3) | ((j2 & 3) << 1);
                        #pragma unroll
                        for (int e2 = 0; e2 < 2; e2++) {
                            if (!((msk >> (16 * e2)) & 0xFFFFu)) continue;
                            unsigned int h = (u >> (16 * e2)) & 0xFFFFu;
                            unsigned int pk = (fkey16(h) << 16) |
                                (unsigned int)(2047 - (tb + kcol + e2));
                            if (pk > lst[TOPK - 1]) {
                                unsigned int cur = pk;
                                #pragma unroll
                                for (int i = 0; i < TOPK; i++) {
                                    unsigned int old = lst[i];
                                    bool g = cur > old;
                                    lst[i] = g ? cur : old;
                                    cur = g ? old : cur;
                                }
                                unsigned int tk2 = lst[TOPK - 1] >> 16;
                                unsigned int th2v = tk2 ? unfkey16(tk2) : 0xFC00u;
                                thr2 = __half2half2(
                                    __ushort_as_half((unsigned short)th2v));
                            }
                        }
                    }
                }
                __syncwarp();
            }
        }

        // writeout: unpack fp16 key + idx -> g_cand u64 format
        {
            int b = qbase + tid;
            unsigned long long* dst = &g_cand[((size_t)b * NCHUNKS + chunk) * TOPK];
            #pragma unroll
            for (int j = 0; j < TOPK; j++) {
                unsigned int e = lst[j];
                unsigned int h = unfkey16(e >> 16);
                float vv = __half2float(__ushort_as_half((unsigned short)h));
                int kidx = c0 + 2047 - (int)(e & 0x7FFu);
                dst[j] = ((unsigned long long)fkey(vv) << 32) |
                         (unsigned long long)(0xFFFFFFFFu - (unsigned int)kidx);
            }
        }
    }
}

// -------- kernel 4: merge approx top-48, exact rescore, output --------
#define NCAND (NCHUNKS * TOPK)   // 1568

__global__ void __launch_bounds__(128)
k_rescore(const float* __restrict__ keys, const float* __restrict__ values,
          float* __restrict__ out) {
    __shared__ unsigned long long cb[NCAND];
    __shared__ unsigned long long wred[4];
    __shared__ unsigned long long mtop[MTOP];
    __shared__ unsigned long long exact[MTOP];
    __shared__ float qsh[DDIM];
    __shared__ float smv[TOPK];
    __shared__ int   sidx[TOPK];
    __shared__ float w[TOPK];

    int b = blockIdx.x, tid = threadIdx.x;
    int lane = tid & 31, warp = tid >> 5;

    const unsigned long long* src = &g_cand[(size_t)b * NCAND];
    for (int i = tid; i < NCAND; i += 128) cb[i] = src[i];
    qsh[tid] = g_qn[b * DDIM + tid];
    __syncthreads();

    for (int r = 0; r < MTOP; r++) {
        unsigned long long m = 0ull;
        for (int i = tid; i < NCAND; i += 128) {
            unsigned long long v = cb[i];
            if (v > m) m = v;
        }
        #pragma unroll
        for (int o = 16; o; o >>= 1) {
            unsigned long long t = __shfl_xor_sync(0xffffffffu, m, o);
            if (t > m) m = t;
        }
        if (lane == 0) wred[warp] = m;
        __syncthreads();
        unsigned long long top = wred[0];
        #pragma unroll
        for (int i = 1; i < 4; i++) if (wred[i] > top) top = wred[i];
        for (int i = tid; i < NCAND; i += 128)
            if (cb[i] == top) cb[i] = 0ull;
        if (tid == 0) mtop[r] = top;
        __syncthreads();
    }

    for (int r = warp; r < MTOP; r += 4) {
        unsigned long long pk = mtop[r];
        int key = (int)(0xFFFFFFFFu - (unsigned int)(pk & 0xFFFFFFFFu));
        float4 kv = ((const float4*)(keys + (size_t)key * DDIM))[lane];
        float4 qv = *(const float4*)&qsh[lane * 4];
        float d = kv.x * qv.x + kv.y * qv.y + kv.z * qv.z + kv.w * qv.w;
        #pragma unroll
        for (int o = 16; o; o >>= 1) d += __shfl_xor_sync(0xffffffffu, d, o);
        if (lane == 0) {
            float ex = d * g_scale[key];
            exact[r] = ((unsigned long long)fkey(ex) << 32) |
                       (unsigned long long)(0xFFFFFFFFu - (unsigned int)key);
        }
    }
    __syncthreads();

    if (warp == 0) {
        unsigned long long va = exact[lane];
        unsigned long long vb = (lane + 32 < MTOP) ? exact[lane + 32] : 0ull;
        for (int r = 0; r < TOPK; r++) {
            unsigned long long m = (va > vb) ? va : vb;
            #pragma unroll
            for (int o = 16; o; o >>= 1) {
                unsigned long long t = __shfl_xor_sync(0xffffffffu, m, o);
                if (t > m) m = t;
            }
            if (va == m) va = 0ull;
            else if (vb == m) vb = 0ull;
            if (lane == 0) {
                float s = funkey((unsigned int)(m >> 32));
                int idx = (int)(0xFFFFFFFFu - (unsigned int)(m & 0xFFFFFFFFu));
                smv[r] = (s >= 0.0f) ? s : 0.0f;
                sidx[r] = idx;
            }
        }
        if (lane == 0) {
            float su = 0.0f;
            #pragma unroll
            for (int r = 0; r < TOPK; r++) su += smv[r];
            su += 1e-8f;
            #pragma unroll
            for (int r = 0; r < TOPK; r++) w[r] = smv[r] / su;
        }
    }
    __syncthreads();

    for (int j = tid; j < HFDIM; j += 128) {
        float a = 0.0f;
        #pragma unroll
        for (int r = 0; r < TOPK; r++)
            a += w[r] * values[(size_t)sidx[r] * HFDIM + j];
        out[(size_t)b * HFDIM + j] = a;
    }
}

// -------- launch --------
extern "C" void kernel_launch(void* const* d_in, const int* in_sizes, int n_in,
                              void* d_out, int out_size) {
    const float* query  = (const float*)d_in[0];
    const float* keys   = (const float*)d_in[1];
    const float* values = (const float*)d_in[2];
    const void*  ts     = d_in[3];
    const int*   gsp    = (n_in > 4) ? (const int*)d_in[4] : nullptr;

    cudaFuncSetAttribute(k_filter,
                         cudaFuncAttributeMaxDynamicSharedMemorySize, SMEM_SZ);

    k_detect<<<1, 32>>>((const unsigned int*)ts);
    k_normq<<<BQ, DDIM>>>(query);
    k_scale<<<(NKEYS * 32 + 255) / 256, 256>>>(keys, ts, gsp, gsp != nullptr);
    k_filter<<<GRID_F, FTHR, SMEM_SZ>>>();
    k_rescore<<<BQ, 128>>>(keys, values, (float*)d_out);
}

// round 17
// speedup vs baseline: 1.1863x; 1.1863x over previous
#include <cuda_runtime.h>
#include <cuda_fp16.h>
#include <math.h>

// Problem constants
#define BQ      1024
#define DDIM    128
#define NKEYS   200000
#define HFDIM   168
#define TOPK    16
#define MTOP    48
#define CHUNK   4096
#define NCHUNKS 49           // 48*4096 + 3392; 3392 = 53*64 (all tiles full)
#define QTILES  8
#define NPAIRS  (QTILES*NCHUNKS)   // 392
#define FTHR    128
#define GRID_F  392          // one work item per block, single wave @3/SM

// -------- filter kernel SMEM layout (bytes) --------
// [Ks fp16 2x64x136 (34816, unioned with Qs 128x136) | SimU u32 128x37 | work]
#define KBUF_B    17408
#define OFF_SIM   34816
#define OFF_WORK  53760
#define SMEM_SZ   53776

// -------- scratch --------
__device__ float g_qn[BQ * DDIM];
__device__ __half g_qh[BQ * DDIM];
__device__ __half g_khd[(size_t)NKEYS * DDIM];
__device__ float g_scale[NKEYS];
__device__ unsigned long long g_cand[(size_t)BQ * NCHUNKS * TOPK];
__device__ int g_ts64;
__device__ unsigned int g_work;

// -------- helpers --------
__device__ __forceinline__ unsigned int fkey(float f) {
    unsigned int u = __float_as_uint(f);
    return (u & 0x80000000u) ? ~u : (u | 0x80000000u);
}
__device__ __forceinline__ float funkey(unsigned int u) {
    return (u & 0x80000000u) ? __uint_as_float(u ^ 0x80000000u)
                             : __uint_as_float(~u);
}
__device__ __forceinline__ unsigned int fkey16(unsigned int h) {
    return (h & 0x8000u) ? (h ^ 0xFFFFu) : (h | 0x8000u);
}
__device__ __forceinline__ unsigned int unfkey16(unsigned int k16) {
    return (k16 & 0x8000u) ? (k16 ^ 0x8000u) : (k16 ^ 0xFFFFu);
}
__device__ __forceinline__ unsigned int su32(const void* p) {
    unsigned int r;
    asm("{.reg .u64 t; cvta.to.shared.u64 t, %1; cvt.u32.u64 %0, t;}"
        : "=r"(r) : "l"(p));
    return r;
}
__device__ __forceinline__ void cp16(unsigned int dst, const void* src) {
    asm volatile("cp.async.cg.shared.global [%0], [%1], 16;"
                 :: "r"(dst), "l"(src));
}
#define CP_COMMIT() asm volatile("cp.async.commit_group;")
#define CP_WAIT0()  asm volatile("cp.async.wait_group 0;" ::: "memory")

#define LDSM_X4(f, ad) \
    asm volatile("ldmatrix.sync.aligned.m8n8.x4.shared.b16 {%0,%1,%2,%3}, [%4];" \
        : "=r"((f)[0]), "=r"((f)[1]), "=r"((f)[2]), "=r"((f)[3]) : "r"(ad))
#define MMA_F16(c0, c1, a, b0, b1) \
    asm volatile("mma.sync.aligned.m16n8k16.row.col.f16.f16.f16.f16 " \
        "{%0,%1}, {%2,%3,%4,%5}, {%6,%7}, {%0,%1};" \
        : "+r"(c0), "+r"(c1) \
        : "r"((a)[0]), "r"((a)[1]), "r"((a)[2]), "r"((a)[3]), "r"(b0), "r"(b1))

// -------- kernel 0: detect ts dtype + reset work counter --------
__global__ void k_detect(const unsigned int* tsw) {
    if (threadIdx.x == 0) {
        int all0 = 1;
        for (int i = 0; i < 64; i++)
            if (tsw[2 * i + 1] != 0u) { all0 = 0; break; }
        g_ts64 = all0;
        g_work = 0u;
    }
}

// -------- kernel 1: normalize queries (fp32 + fp16) --------
__global__ void k_normq(const float* __restrict__ query) {
    int b = blockIdx.x;
    int d = threadIdx.x;
    float v = query[b * DDIM + d];
    float s = v * v;
    #pragma unroll
    for (int o = 16; o; o >>= 1) s += __shfl_xor_sync(0xffffffffu, s, o);
    __shared__ float ws[4];
    if ((d & 31) == 0) ws[d >> 5] = s;
    __syncthreads();
    float tot = ws[0] + ws[1] + ws[2] + ws[3];
    float n = fmaxf(sqrtf(tot), 1e-12f);
    float q = v / n;
    g_qn[b * DDIM + d] = q;
    g_qh[b * DDIM + d] = __float2half_rn(q);
}

// -------- kernel 2: per-key scale + fp16 decayed keys --------
__global__ void k_scale(const float* __restrict__ keys, const void* ts,
                        const int* gsp, int has_gs) {
    int gw = (blockIdx.x * blockDim.x + threadIdx.x) >> 5;
    int lane = threadIdx.x & 31;
    if (gw >= NKEYS) return;
    float4 a = ((const float4*)(keys + (size_t)gw * DDIM))[lane];
    float s = a.x * a.x + a.y * a.y + a.z * a.z + a.w * a.w;
    #pragma unroll
    for (int o = 16; o; o >>= 1) s += __shfl_xor_sync(0xffffffffu, s, o);
    float sc;
    if (lane == 0) {
        long long t = g_ts64 ? ((const long long*)ts)[gw]
                             : (long long)((const int*)ts)[gw];
        int gs = has_gs ? gsp[0] : 1000;
        float age = (float)(gs - (int)t);
        float dec = powf(0.995f, age);
        float nr = fmaxf(sqrtf(s), 1e-12f);
        sc = dec / nr;
        g_scale[gw] = sc;
    }
    sc = __shfl_sync(0xffffffffu, sc, 0);
    __half2 p0 = __floats2half2_rn(a.x * sc, a.y * sc);
    __half2 p1 = __floats2half2_rn(a.z * sc, a.w * sc);
    uint2 pk = make_uint2(*(unsigned int*)&p0, *(unsigned int*)&p1);
    *(uint2*)&g_khd[(size_t)gw * DDIM + lane * 4] = pk;
}

// -------- kernel 3: fp16 MMA filter, register top-16 lists --------
__global__ void __launch_bounds__(FTHR, 3)
k_filter() {
    extern __shared__ __align__(16) unsigned char sm[];
    __half* Ks  = (__half*)sm;                     // [2][64][136]
    __half* Qs  = (__half*)sm;                     // [128][136] (prologue union)
    unsigned int* SimU = (unsigned int*)(sm + OFF_SIM);  // [128][37]
    unsigned int* swork = (unsigned int*)(sm + OFF_WORK);

    unsigned int ks_base = su32(Ks);
    int tid  = threadIdx.x;
    int warp = tid >> 5;
    int lane = tid & 31;
    int q0 = warp * 32;
    int qr = lane >> 2;
    int qc = lane & 3;

    for (;;) {
        __syncthreads();
        if (tid == 0) *swork = atomicAdd(&g_work, 1u);
        __syncthreads();
        unsigned int p = *swork;
        if (p >= NPAIRS) break;
        int chunk = p >> 3;
        int qtile = p & 7;
        int qbase = qtile * 128;
        int c0 = chunk * CHUNK;
        int ntiles = (chunk == NCHUNKS - 1) ? 53 : 64;

        // register top-16 list (packed: fkey16(val)<<16 | (4095-localidx))
        unsigned int lst[TOPK];
        #pragma unroll
        for (int j = 0; j < TOPK; j++) lst[j] = 0u;

        // prologue: stage Q [128][128] fp16 through the K double-buffer region
        for (int i = tid; i < 128 * 16; i += FTHR) {
            int row = i >> 4, c = i & 15;
            *(uint4*)(Qs + row * 136 + c * 8) =
                *(const uint4*)(g_qh + (qbase + row) * DDIM + c * 8);
        }
        __syncthreads();
        unsigned int afr[16][4];
        #pragma unroll
        for (int s8 = 0; s8 < 8; s8++) {
            #pragma unroll
            for (int mi = 0; mi < 2; mi++) {
                int row = q0 + mi * 16 + (lane & 15);
                int col = s8 * 16 + ((lane >> 4) << 3);
                LDSM_X4(afr[mi * 8 + s8], su32(Qs + row * 136 + col));
            }
        }
        __syncthreads();   // A frags read before K tile 0 overwrites

        // issue K tile 0 into buffer 0
        #pragma unroll
        for (int it = 0; it < 8; it++) {
            int i = tid + it * FTHR;
            int row = i >> 4, c = i & 15;
            cp16(ks_base + row * 272 + c * 16,
                 g_khd + (size_t)(c0 + row) * DDIM + c * 8);
        }
        CP_COMMIT();

        for (int t = 0; t < ntiles; t++) {
            unsigned int kb = ks_base + (t & 1) * KBUF_B;
            CP_WAIT0();
            __syncthreads();   // tile t ready; all warps done with tile t-1

            if (t + 1 < ntiles) {
                int n1 = c0 + (t + 1) * 64;
                unsigned int ob = ks_base + ((t + 1) & 1) * KBUF_B;
                #pragma unroll
                for (int it = 0; it < 8; it++) {
                    int i = tid + it * FTHR;
                    int row = i >> 4, c = i & 15;
                    cp16(ob + row * 272 + c * 16,
                         g_khd + (size_t)(n1 + row) * DDIM + c * 8);
                }
            }
            CP_COMMIT();

            // fp16-acc MMA over 8 k-steps
            unsigned int acc[2][8][2];
            #pragma unroll
            for (int mi = 0; mi < 2; mi++)
                #pragma unroll
                for (int nt = 0; nt < 8; nt++) {
                    acc[mi][nt][0] = 0u;
                    acc[mi][nt][1] = 0u;
                }
            #pragma unroll
            for (int s8 = 0; s8 < 8; s8++) {
                unsigned int bb[4][4];
                int prow = (lane & 7) + ((lane >> 4) << 3);
                int pcol = s8 * 16 + (((lane >> 3) & 1) << 3);
                #pragma unroll
                for (int g = 0; g < 4; g++)
                    LDSM_X4(bb[g], kb + (g * 16 + prow) * 272 + pcol * 2);
                #pragma unroll
                for (int mi = 0; mi < 2; mi++) {
                    const unsigned int* a = afr[mi * 8 + s8];
                    #pragma unroll
                    for (int nt = 0; nt < 8; nt++) {
                        unsigned int b0 = bb[nt >> 1][(nt & 1) * 2];
                        unsigned int b1 = bb[nt >> 1][(nt & 1) * 2 + 1];
                        MMA_F16(acc[mi][nt][0], acc[mi][nt][1], a, b0, b1);
                    }
                }
            }

            // register rowmax per covered row (mx[mi*2+e] covers row qr+e*8+mi*16)
            float mx[4];
            #pragma unroll
            for (int mi = 0; mi < 2; mi++) {
                #pragma unroll
                for (int e = 0; e < 2; e++) {
                    __half2 m = *(__half2*)&acc[mi][0][e];
                    #pragma unroll
                    for (int nt = 1; nt < 8; nt++)
                        m = __hmax2(m, *(__half2*)&acc[mi][nt][e]);
                    float mv = fmaxf(__low2float(m), __high2float(m));
                    mv = fmaxf(mv, __shfl_xor_sync(0xffffffffu, mv, 1));
                    mv = fmaxf(mv, __shfl_xor_sync(0xffffffffu, mv, 2));
                    mx[mi * 2 + e] = mv;
                }
            }
            // route rowmax to owner lane (lane L owns row q0+L)
            int srcl = (lane & 7) * 4;
            float m0 = __shfl_sync(0xffffffffu, mx[0], srcl);
            float m1 = __shfl_sync(0xffffffffu, mx[1], srcl);
            float m2 = __shfl_sync(0xffffffffu, mx[2], srcl);
            float m3 = __shfl_sync(0xffffffffu, mx[3], srcl);
            int ksel = ((lane >> 4) << 1) | ((lane >> 3) & 1);
            float mymax = (ksel == 0) ? m0 : (ksel == 1) ? m1
                        : (ksel == 2) ? m2 : m3;
            unsigned int rowpk =
                (fkey16((unsigned int)__half_as_ushort(__float2half_rn(mymax)))
                 << 16) | 0xFFFu;
            unsigned int myflag = (rowpk > lst[TOPK - 1]) ? 1u : 0u;
            unsigned int flags = __ballot_sync(0xffffffffu, myflag);

            if (flags) {
                // predicated stores of flagged rows (u32 cols nt*4+qc)
                #pragma unroll
                for (int mi = 0; mi < 2; mi++)
                    #pragma unroll
                    for (int e = 0; e < 2; e++) {
                        int rr = qr + e * 8 + mi * 16;
                        if ((flags >> rr) & 1u) {
                            unsigned int* dst = SimU + (q0 + rr) * 37 + qc;
                            #pragma unroll
                            for (int nt = 0; nt < 8; nt++)
                                dst[nt * 4] = acc[mi][nt][e];
                        }
                    }
                __syncwarp();
                if (myflag) {
                    const unsigned int* rowu = SimU + (q0 + lane) * 37;
                    int tb = t * 64;
                    for (int j2 = 0; j2 < 32; j2++) {
                        unsigned int u = rowu[j2];
                        int kcol = ((j2 >> 2) << 3) | ((j2 & 3) << 1);
                        #pragma unroll
                        for (int e2 = 0; e2 < 2; e2++) {
                            unsigned int h = (u >> (16 * e2)) & 0xFFFFu;
                            unsigned int pk = (fkey16(h) << 16) |
                                (unsigned int)(4095 - (tb + kcol + e2));
                            if (pk > lst[TOPK - 1]) {
                                unsigned int cur = pk;
                                #pragma unroll
                                for (int i = 0; i < TOPK; i++) {
                                    unsigned int old = lst[i];
                                    bool g = cur > old;
                                    lst[i] = g ? cur : old;
                                    cur = g ? old : cur;
                                }
                            }
                        }
                    }
                }
                __syncwarp();
            }
        }

        // writeout: unpack fp16 key + idx -> g_cand u64 format
        {
            int b = qbase + tid;
            unsigned long long* dst = &g_cand[((size_t)b * NCHUNKS + chunk) * TOPK];
            #pragma unroll
            for (int j = 0; j < TOPK; j++) {
                unsigned int e = lst[j];
                unsigned int h = unfkey16(e >> 16);
                float vv = __half2float(__ushort_as_half((unsigned short)h));
                int kidx = c0 + 4095 - (int)(e & 0xFFFu);
                dst[j] = ((unsigned long long)fkey(vv) << 32) |
                         (unsigned long long)(0xFFFFFFFFu - (unsigned int)kidx);
            }
        }
    }
}

// -------- kernel 4: merge approx top-48, exact rescore, output --------
#define NCAND (NCHUNKS * TOPK)   // 784

__global__ void __launch_bounds__(128)
k_rescore(const float* __restrict__ keys, const float* __restrict__ values,
          float* __restrict__ out) {
    __shared__ unsigned long long cb[NCAND];
    __shared__ unsigned long long wred[4];
    __shared__ unsigned long long mtop[MTOP];
    __shared__ unsigned long long exact[MTOP];
    __shared__ float qsh[DDIM];
    __shared__ float smv[TOPK];
    __shared__ int   sidx[TOPK];
    __shared__ float w[TOPK];

    int b = blockIdx.x, tid = threadIdx.x;
    int lane = tid & 31, warp = tid >> 5;

    const unsigned long long* src = &g_cand[(size_t)b * NCAND];
    for (int i = tid; i < NCAND; i += 128) cb[i] = src[i];
    qsh[tid] = g_qn[b * DDIM + tid];
    __syncthreads();

    for (int r = 0; r < MTOP; r++) {
        unsigned long long m = 0ull;
        for (int i = tid; i < NCAND; i += 128) {
            unsigned long long v = cb[i];
            if (v > m) m = v;
        }
        #pragma unroll
        for (int o = 16; o; o >>= 1) {
            unsigned long long t = __shfl_xor_sync(0xffffffffu, m, o);
            if (t > m) m = t;
        }
        if (lane == 0) wred[warp] = m;
        __syncthreads();
        unsigned long long top = wred[0];
        #pragma unroll
        for (int i = 1; i < 4; i++) if (wred[i] > top) top = wred[i];
        for (int i = tid; i < NCAND; i += 128)
            if (cb[i] == top) cb[i] = 0ull;
        if (tid == 0) mtop[r] = top;
        __syncthreads();
    }

    for (int r = warp; r < MTOP; r += 4) {
        unsigned long long pk = mtop[r];
        int key = (int)(0xFFFFFFFFu - (unsigned int)(pk & 0xFFFFFFFFu));
        float4 kv = ((const float4*)(keys + (size_t)key * DDIM))[lane];
        float4 qv = *(const float4*)&qsh[lane * 4];
        float d = kv.x * qv.x + kv.y * qv.y + kv.z * qv.z + kv.w * qv.w;
        #pragma unroll
        for (int o = 16; o; o >>= 1) d += __shfl_xor_sync(0xffffffffu, d, o);
        if (lane == 0) {
            float ex = d * g_scale[key];
            exact[r] = ((unsigned long long)fkey(ex) << 32) |
                       (unsigned long long)(0xFFFFFFFFu - (unsigned int)key);
        }
    }
    __syncthreads();

    if (warp == 0) {
        unsigned long long va = exact[lane];
        unsigned long long vb = (lane + 32 < MTOP) ? exact[lane + 32] : 0ull;
        for (int r = 0; r < TOPK; r++) {
            unsigned long long m = (va > vb) ? va : vb;
            #pragma unroll
            for (int o = 16; o; o >>= 1) {
                unsigned long long t = __shfl_xor_sync(0xffffffffu, m, o);
                if (t > m) m = t;
            }
            if (va == m) va = 0ull;
            else if (vb == m) vb = 0ull;
            if (lane == 0) {
                float s = funkey((unsigned int)(m >> 32));
                int idx = (int)(0xFFFFFFFFu - (unsigned int)(m & 0xFFFFFFFFu));
                smv[r] = (s >= 0.0f) ? s : 0.0f;
                sidx[r] = idx;
            }
        }
        if (lane == 0) {
            float su = 0.0f;
            #pragma unroll
            for (int r = 0; r < TOPK; r++) su += smv[r];
            su += 1e-8f;
            #pragma unroll
            for (int r = 0; r < TOPK; r++) w[r] = smv[r] / su;
        }
    }
    __syncthreads();

    for (int j = tid; j < HFDIM; j += 128) {
        float a = 0.0f;
        #pragma unroll
        for (int r = 0; r < TOPK; r++)
            a += w[r] * values[(size_t)sidx[r] * HFDIM + j];
        out[(size_t)b * HFDIM + j] = a;
    }
}

// -------- launch --------
extern "C" void kernel_launch(void* const* d_in, const int* in_sizes, int n_in,
                              void* d_out, int out_size) {
    const float* query  = (const float*)d_in[0];
    const float* keys   = (const float*)d_in[1];
    const float* values = (const float*)d_in[2];
    const void*  ts     = d_in[3];
    const int*   gsp    = (n_in > 4) ? (const int*)d_in[4] : nullptr;

    cudaFuncSetAttribute(k_filter,
                         cudaFuncAttributeMaxDynamicSharedMemorySize, SMEM_SZ);

    k_detect<<<1, 32>>>((const unsigned int*)ts);
    k_normq<<<BQ, DDIM>>>(query);
    k_scale<<<(NKEYS * 32 + 255) / 256, 256>>>(keys, ts, gsp, gsp != nullptr);
    k_filter<<<GRID_F, FTHR, SMEM_SZ>>>();
    k_rescore<<<BQ, 128>>>(keys, values, (float*)d_out);
}